// round 3
// baseline (speedup 1.0000x reference)
#include <cuda_runtime.h>
#include <math_constants.h>

// ---------------- problem constants (fixed shapes) ----------------
#define N_NODES  8192
#define N_EDGES  262144
#define IN_C     64
#define OUT_C    64
#define DIN      192          // IN_C * K
#define DOUT     192          // OUT_C * K
#define G_GRAPHS 64
#define D3       576          // 3 * DOUT
#define H1DIM    384
#define H2DIM    192
#define NCLS     10
#define BN_EPS   1e-5f

// ---------------- device scratch (no allocations allowed) ----------------
__device__ float g_deg[N_NODES];
__device__ float g_dinv[N_NODES];
__device__ int   g_rowPtr[N_NODES + 1];
__device__ int   g_rowCnt[N_NODES];
__device__ int   g_colIdx[N_EDGES];
__device__ float g_val[N_EDGES];
__device__ float g_Hcat[N_NODES * DIN];   // [x | Lx | L^2 x]
__device__ float g_H[N_NODES * DOUT];     // after masked linear
__device__ float g_Ws[DOUT * DIN];        // masked, sigma-scaled W
__device__ float g_sigma;
__device__ float g_sum[DOUT], g_sumsq[DOUT], g_mu[DOUT], g_rstd[DOUT];
__device__ int   g_segStart[G_GRAPHS + 1];
__device__ float g_Hg[G_GRAPHS * D3];
__device__ float g_xo[G_GRAPHS * D3];
__device__ float g_a1[G_GRAPHS * H1DIM];
__device__ float g_a2[G_GRAPHS * H2DIM];

// ---------------- kernels ----------------

__global__ void k_init() {
    int i = blockIdx.x * blockDim.x + threadIdx.x;
    if (i < N_NODES) { g_deg[i] = 0.f; g_rowCnt[i] = 0; }
    if (i < DOUT)    { g_sum[i] = 0.f; g_sumsq[i] = 0.f; }
}

__global__ void k_degree(const int* __restrict__ ei) {
    int e = blockIdx.x * blockDim.x + threadIdx.x;
    if (e < N_EDGES) atomicAdd(&g_deg[ei[e]], 1.0f);
}

__global__ void k_dinv() {
    int i = blockIdx.x * blockDim.x + threadIdx.x;
    if (i < N_NODES) {
        float d = g_deg[i];
        g_dinv[i] = (d > 0.f) ? rsqrtf(fmaxf(d, 1.f)) : 0.f;
    }
}

// one-block exclusive scan of (int)deg -> rowPtr (8192 = 1024 * 8)
__global__ void k_scan() {
    __shared__ int part[1024];
    int t = threadIdx.x;
    int base = t * 8;
    int loc[8]; int s = 0;
#pragma unroll
    for (int j = 0; j < 8; ++j) { loc[j] = s; s += (int)g_deg[base + j]; }
    part[t] = s;
    __syncthreads();
    for (int off = 1; off < 1024; off <<= 1) {
        int v = (t >= off) ? part[t - off] : 0;
        __syncthreads();
        part[t] += v;
        __syncthreads();
    }
    int cb = (t == 0) ? 0 : part[t - 1];
#pragma unroll
    for (int j = 0; j < 8; ++j) g_rowPtr[base + j] = cb + loc[j];
    if (t == 1023) g_rowPtr[N_NODES] = part[1023];
}

__global__ void k_build(const int* __restrict__ ei) {
    int e = blockIdx.x * blockDim.x + threadIdx.x;
    if (e >= N_EDGES) return;
    int r = ei[e];
    int c = ei[N_EDGES + e];
    int pos = g_rowPtr[r] + atomicAdd(&g_rowCnt[r], 1);
    g_colIdx[pos] = c;
    g_val[pos] = -g_dinv[r] * g_dinv[c];
}

__global__ void k_copyx(const float* __restrict__ x) {
    int idx = blockIdx.x * blockDim.x + threadIdx.x;
    if (idx < N_NODES * IN_C) {
        int i = idx >> 6, f = idx & 63;
        g_Hcat[i * DIN + f] = x[idx];
    }
}

// gather SpMM: dst = src + L_offdiag @ src  (warp per row, lane = 2 features)
__global__ void k_spmm(int srcOff, int dstOff) {
    int w = (blockIdx.x * blockDim.x + threadIdx.x) >> 5;
    int lane = threadIdx.x & 31;
    if (w >= N_NODES) return;
    float2 acc = *(const float2*)&g_Hcat[w * DIN + srcOff + 2 * lane];
    int s = g_rowPtr[w], e = g_rowPtr[w + 1];
    for (int p = s; p < e; ++p) {
        int c = __ldg(&g_colIdx[p]);
        float v = __ldg(&g_val[p]);
        float2 xv = *(const float2*)&g_Hcat[c * DIN + srcOff + 2 * lane];
        acc.x = fmaf(v, xv.x, acc.x);
        acc.y = fmaf(v, xv.y, acc.y);
    }
    *(float2*)&g_Hcat[w * DIN + dstOff + 2 * lane] = acc;
}

// sigma = u.(W v_hat) = ||W^T u||^2 / (||W^T u|| + 1e-12)
__global__ void k_sigma(const float* __restrict__ W, const float* __restrict__ u) {
    __shared__ float red[256];
    int t = threadIdx.x;
    float vsq = 0.f;
    if (t < DIN) {
        float v = 0.f;
        for (int i = 0; i < DOUT; ++i) v += W[i * DIN + t] * u[i];
        vsq = v * v;
    }
    red[t] = vsq;
    __syncthreads();
    for (int off = 128; off; off >>= 1) {
        if (t < off) red[t] += red[t + off];
        __syncthreads();
    }
    if (t == 0) {
        float ns = red[0];
        g_sigma = ns / (sqrtf(ns) + 1e-12f);
    }
}

__global__ void k_maskW(const float* __restrict__ W) {
    int idx = blockIdx.x * blockDim.x + threadIdx.x;
    if (idx < DOUT * DIN) {
        int r = idx / DIN, c = idx % DIN;
        g_Ws[idx] = (c < IN_C * (r / OUT_C + 1)) ? (W[idx] / g_sigma) : 0.f;
    }
}

// H = Hcat @ Ws^T + b ; 64x64 tiles, mask-aware K limit
__global__ void k_gemm(const float* __restrict__ bias) {
    const int m0 = blockIdx.x * 64;
    const int n0 = blockIdx.y * 64;
    const int Klim = 64 * (blockIdx.y + 1);
    __shared__ float As[32][65];
    __shared__ float Bs[32][65];
    const int tid = threadIdx.x;                // 256
    const int tx = tid & 15, ty = tid >> 4;
    float acc[4][4] = {};
    for (int k0 = 0; k0 < Klim; k0 += 32) {
#pragma unroll
        for (int r = 0; r < 8; ++r) {
            int e = tid + r * 256;
            int m = e >> 5, k = e & 31;
            As[k][m] = g_Hcat[(m0 + m) * DIN + k0 + k];
            Bs[k][m] = g_Ws[(n0 + m) * DIN + k0 + k];
        }
        __syncthreads();
#pragma unroll
        for (int k = 0; k < 32; ++k) {
            float a[4], bb[4];
#pragma unroll
            for (int j = 0; j < 4; ++j) { a[j] = As[k][ty * 4 + j]; bb[j] = Bs[k][tx * 4 + j]; }
#pragma unroll
            for (int i = 0; i < 4; ++i)
#pragma unroll
                for (int j = 0; j < 4; ++j) acc[i][j] = fmaf(a[i], bb[j], acc[i][j]);
        }
        __syncthreads();
    }
#pragma unroll
    for (int i = 0; i < 4; ++i) {
        int m = m0 + ty * 4 + i;
#pragma unroll
        for (int j = 0; j < 4; ++j) {
            int n = n0 + tx * 4 + j;
            g_H[m * DOUT + n] = acc[i][j] + bias[n];
        }
    }
}

__global__ void k_bn1stats() {
    int c = threadIdx.x;                        // 192
    int r0 = blockIdx.x * 64;
    float s = 0.f, ss = 0.f;
    for (int r = r0; r < r0 + 64; ++r) {
        float v = g_H[r * DOUT + c];
        s += v; ss += v * v;
    }
    atomicAdd(&g_sum[c], s);
    atomicAdd(&g_sumsq[c], ss);
}

__global__ void k_bn1fin() {
    int c = threadIdx.x;                        // 192
    float mu = g_sum[c] / (float)N_NODES;
    float var = g_sumsq[c] / (float)N_NODES - mu * mu;
    g_mu[c] = mu;
    g_rstd[c] = rsqrtf(var + BN_EPS);
}

__global__ void k_segb(const int* __restrict__ batch) {
    int t = threadIdx.x;
    if (t > G_GRAPHS) return;
    int lo = 0, hi = N_NODES;
    while (lo < hi) {
        int mid = (lo + hi) >> 1;
        if (batch[mid] < t) lo = mid + 1; else hi = mid;
    }
    g_segStart[t] = lo;
}

// BN1 + segment avg/sum/max, deterministic (block per graph, thread per column)
__global__ void k_pool(const float* __restrict__ gamma, const float* __restrict__ beta) {
    int g = blockIdx.x, c = threadIdx.x;        // 192 threads
    int s = g_segStart[g], e = g_segStart[g + 1];
    float ga = gamma[c], be = beta[c], mu = g_mu[c], rs = g_rstd[c];
    float sum = 0.f, mx = -CUDART_INF_F;
    for (int r = s; r < e; ++r) {
        float v = ga * (g_H[r * DOUT + c] - mu) * rs + be;
        sum += v;
        mx = fmaxf(mx, v);
    }
    float cnt = (float)(e - s);
    g_Hg[g * D3 + c]            = sum / fmaxf(cnt, 1.f);
    g_Hg[g * D3 + DOUT + c]     = sum;
    g_Hg[g * D3 + 2 * DOUT + c] = mx;
}

__global__ void k_bn2(const float* __restrict__ gamma, const float* __restrict__ beta) {
    int c = threadIdx.x;                        // 576
    float s = 0.f, ss = 0.f;
    for (int r = 0; r < G_GRAPHS; ++r) {
        float v = g_Hg[r * D3 + c];
        s += v; ss += v * v;
    }
    float mu = s / (float)G_GRAPHS;
    float var = ss / (float)G_GRAPHS - mu * mu;
    float rs = rsqrtf(var + BN_EPS);
    float ga = gamma[c], be = beta[c];
    for (int r = 0; r < G_GRAPHS; ++r)
        g_xo[r * D3 + c] = ga * (g_Hg[r * D3 + c] - mu) * rs + be;
}

// fc1: [64,576] -> relu([64,384]); 4 rows per block
__global__ void k_fc1(const float* __restrict__ w1, const float* __restrict__ b1) {
    __shared__ float sx[4][D3];
    int r0 = blockIdx.x * 4;
    for (int e = threadIdx.x; e < 4 * D3; e += blockDim.x)
        sx[e / D3][e % D3] = g_xo[(r0 + e / D3) * D3 + (e % D3)];
    __syncthreads();
    int o = threadIdx.x;                        // 384
    float a0 = b1[o], a1 = b1[o], a2 = b1[o], a3 = b1[o];
    const float4* wr = (const float4*)&w1[o * D3];
    for (int k4 = 0; k4 < D3 / 4; ++k4) {
        float4 w = wr[k4];
        int k = k4 * 4;
        a0 += w.x * sx[0][k] + w.y * sx[0][k + 1] + w.z * sx[0][k + 2] + w.w * sx[0][k + 3];
        a1 += w.x * sx[1][k] + w.y * sx[1][k + 1] + w.z * sx[1][k + 2] + w.w * sx[1][k + 3];
        a2 += w.x * sx[2][k] + w.y * sx[2][k + 1] + w.z * sx[2][k + 2] + w.w * sx[2][k + 3];
        a3 += w.x * sx[3][k] + w.y * sx[3][k + 1] + w.z * sx[3][k + 2] + w.w * sx[3][k + 3];
    }
    g_a1[(r0 + 0) * H1DIM + o] = fmaxf(a0, 0.f);
    g_a1[(r0 + 1) * H1DIM + o] = fmaxf(a1, 0.f);
    g_a1[(r0 + 2) * H1DIM + o] = fmaxf(a2, 0.f);
    g_a1[(r0 + 3) * H1DIM + o] = fmaxf(a3, 0.f);
}

// fc2: [64,384] -> relu([64,192]); 4 rows per block
__global__ void k_fc2(const float* __restrict__ w2, const float* __restrict__ b2) {
    __shared__ float sx[4][H1DIM];
    int r0 = blockIdx.x * 4;
    for (int e = threadIdx.x; e < 4 * H1DIM; e += blockDim.x)
        sx[e / H1DIM][e % H1DIM] = g_a1[(r0 + e / H1DIM) * H1DIM + (e % H1DIM)];
    __syncthreads();
    int o = threadIdx.x;                        // 192
    float a0 = b2[o], a1 = b2[o], a2 = b2[o], a3 = b2[o];
    const float4* wr = (const float4*)&w2[o * H1DIM];
    for (int k4 = 0; k4 < H1DIM / 4; ++k4) {
        float4 w = wr[k4];
        int k = k4 * 4;
        a0 += w.x * sx[0][k] + w.y * sx[0][k + 1] + w.z * sx[0][k + 2] + w.w * sx[0][k + 3];
        a1 += w.x * sx[1][k] + w.y * sx[1][k + 1] + w.z * sx[1][k + 2] + w.w * sx[1][k + 3];
        a2 += w.x * sx[2][k] + w.y * sx[2][k + 1] + w.z * sx[2][k + 2] + w.w * sx[2][k + 3];
        a3 += w.x * sx[3][k] + w.y * sx[3][k + 1] + w.z * sx[3][k + 2] + w.w * sx[3][k + 3];
    }
    g_a2[(r0 + 0) * H2DIM + o] = fmaxf(a0, 0.f);
    g_a2[(r0 + 1) * H2DIM + o] = fmaxf(a1, 0.f);
    g_a2[(r0 + 2) * H2DIM + o] = fmaxf(a2, 0.f);
    g_a2[(r0 + 3) * H2DIM + o] = fmaxf(a3, 0.f);
}

// fc3 + log_softmax: one warp per graph
__global__ void k_fc3(const float* __restrict__ w3, const float* __restrict__ b3,
                      float* __restrict__ out) {
    __shared__ float sr[H2DIM];
    int g = blockIdx.x, lane = threadIdx.x;     // 32 threads
    for (int k = lane; k < H2DIM; k += 32) sr[k] = g_a2[g * H2DIM + k];
    __syncwarp();
    float z = -CUDART_INF_F;
    if (lane < NCLS) {
        z = b3[lane];
        for (int k = 0; k < H2DIM; ++k) z = fmaf(w3[lane * H2DIM + k], sr[k], z);
    }
    float mx = z;
    for (int off = 16; off; off >>= 1) mx = fmaxf(mx, __shfl_xor_sync(0xffffffff, mx, off));
    float ex = (lane < NCLS) ? expf(z - mx) : 0.f;
    float sm = ex;
    for (int off = 16; off; off >>= 1) sm += __shfl_xor_sync(0xffffffff, sm, off);
    if (lane < NCLS) out[g * NCLS + lane] = z - mx - logf(sm);
}

// ---------------- launch ----------------
extern "C" void kernel_launch(void* const* d_in, const int* in_sizes, int n_in,
                              void* d_out, int out_size) {
    const float* x     = (const float*)d_in[0];
    const int*   ei    = (const int*)d_in[1];
    const int*   batch = (const int*)d_in[2];
    const float* Wo    = (const float*)d_in[3];
    const float* b     = (const float*)d_in[4];
    const float* u     = (const float*)d_in[5];
    const float* bn1g  = (const float*)d_in[6];
    const float* bn1b  = (const float*)d_in[7];
    const float* bn2g  = (const float*)d_in[8];
    const float* bn2b  = (const float*)d_in[9];
    const float* w1    = (const float*)d_in[10];
    const float* b1    = (const float*)d_in[11];
    const float* w2    = (const float*)d_in[12];
    const float* b2    = (const float*)d_in[13];
    const float* w3    = (const float*)d_in[14];
    const float* b3    = (const float*)d_in[15];
    float*       out   = (float*)d_out;

    k_init<<<(N_NODES + 255) / 256, 256>>>();
    k_degree<<<(N_EDGES + 255) / 256, 256>>>(ei);
    k_dinv<<<(N_NODES + 255) / 256, 256>>>();
    k_scan<<<1, 1024>>>();
    k_build<<<(N_EDGES + 255) / 256, 256>>>(ei);
    k_copyx<<<(N_NODES * IN_C + 255) / 256, 256>>>(x);
    k_spmm<<<(N_NODES * 32) / 256, 256>>>(0, IN_C);        // Lx
    k_spmm<<<(N_NODES * 32) / 256, 256>>>(IN_C, 2 * IN_C); // L^2 x
    k_sigma<<<1, 256>>>(Wo, u);
    k_maskW<<<(DOUT * DIN + 255) / 256, 256>>>(Wo);
    k_gemm<<<dim3(N_NODES / 64, DOUT / 64), 256>>>(b);
    k_bn1stats<<<N_NODES / 64, DOUT>>>();
    k_bn1fin<<<1, DOUT>>>();
    k_segb<<<1, 128>>>(batch);
    k_pool<<<G_GRAPHS, DOUT>>>(bn1g, bn1b);
    k_bn2<<<1, D3>>>(bn2g, bn2b);
    k_fc1<<<G_GRAPHS / 4, H1DIM>>>(w1, b1);
    k_fc2<<<G_GRAPHS / 4, H2DIM>>>(w2, b2);
    k_fc3<<<G_GRAPHS, 32>>>(w3, b3, out);
}

// round 7
// speedup vs baseline: 1.0852x; 1.0852x over previous
#include <cuda_runtime.h>
#include <math_constants.h>

// ---------------- problem constants (fixed shapes) ----------------
#define N_NODES  8192
#define N_EDGES  262144
#define IN_C     64
#define DIN      192          // IN_C * K
#define DOUT     192          // OUT_C * K
#define G_GRAPHS 64
#define D3       576          // 3 * DOUT
#define H1DIM    384
#define H2DIM    192
#define NCLS     10
#define BN_EPS   1e-5f

// ---------------- device scratch (zero-init at module load; funnel re-zeroes) ----
__device__ float g_deg[N_NODES];        // zeroed by tail
__device__ int   g_rowCnt[N_NODES];     // zeroed by tail
__device__ float g_sum[DOUT];           // zeroed by tail
__device__ float g_sumsq[DOUT];         // zeroed by tail
__device__ float g_dinv[N_NODES];
__device__ int   g_rowPtr[N_NODES + 1];
__device__ int   g_colIdx[N_EDGES];
__device__ float g_val[N_EDGES];
__device__ float g_Hcat[N_NODES * DIN];   // [x | Lx | L^2 x]
__device__ float g_H[N_NODES * DOUT];     // after masked linear (+bias)
__device__ float g_sigma;
__device__ float g_Hg[G_GRAPHS * D3];     // [avg | sum | max] per graph

// ---------------- kernels ----------------

__global__ void k_degree(const int* __restrict__ ei) {
    int e = blockIdx.x * blockDim.x + threadIdx.x;
    if (e < N_EDGES) atomicAdd(&g_deg[ei[e]], 1.0f);
}

// dinv + exclusive scan (warp-shuffle) + spectral sigma, one block of 1024
__global__ void k_scan(const float* __restrict__ W, const float* __restrict__ u) {
    __shared__ int   wsum[32];
    __shared__ float fred[256];
    int t = threadIdx.x, lane = t & 31, wid = t >> 5;
    int base = t * 8;
    int loc[8]; int s = 0;
#pragma unroll
    for (int j = 0; j < 8; ++j) {
        float d = g_deg[base + j];
        g_dinv[base + j] = (d > 0.f) ? rsqrtf(fmaxf(d, 1.f)) : 0.f;
        loc[j] = s; s += (int)d;
    }
    // inclusive warp scan of per-thread totals
    int isc = s;
#pragma unroll
    for (int off = 1; off < 32; off <<= 1) {
        int v = __shfl_up_sync(0xffffffff, isc, off);
        if (lane >= off) isc += v;
    }
    if (lane == 31) wsum[wid] = isc;
    __syncthreads();
    if (wid == 0) {
        int v = wsum[lane];
        int sc = v;
#pragma unroll
        for (int off = 1; off < 32; off <<= 1) {
            int q = __shfl_up_sync(0xffffffff, sc, off);
            if (lane >= off) sc += q;
        }
        wsum[lane] = sc - v;   // exclusive warp base
    }
    __syncthreads();
    int tbase = wsum[wid] + (isc - s);   // exclusive thread base
#pragma unroll
    for (int j = 0; j < 8; ++j) g_rowPtr[base + j] = tbase + loc[j];
    if (t == 1023) g_rowPtr[N_NODES] = tbase + s;

    // sigma = ||W^T u||^2 / (||W^T u|| + 1e-12)
    float vsq = 0.f;
    if (t < DIN) {
        float v = 0.f;
        for (int i = 0; i < DOUT; ++i) v = fmaf(W[i * DIN + t], u[i], v);
        vsq = v * v;
    }
    if (t < 256) fred[t] = vsq;
    __syncthreads();
    for (int off = 128; off; off >>= 1) {
        if (t < off) fred[t] += fred[t + off];
        __syncthreads();
    }
    if (t == 0) {
        float ns = fred[0];
        g_sigma = ns / (sqrtf(ns) + 1e-12f);
    }
}

__global__ void k_build(const int* __restrict__ ei) {
    int e = blockIdx.x * blockDim.x + threadIdx.x;
    if (e >= N_EDGES) return;
    int r = ei[e];
    int c = ei[N_EDGES + e];
    int pos = g_rowPtr[r] + atomicAdd(&g_rowCnt[r], 1);
    g_colIdx[pos] = c;
    g_val[pos] = -g_dinv[r] * g_dinv[c];
}

// hop 1: reads x directly, writes Hcat[:,0:64]=x and Hcat[:,64:128]=x+L_off@x
__global__ void k_spmm1(const float* __restrict__ x) {
    int w = (blockIdx.x * blockDim.x + threadIdx.x) >> 5;
    int lane = threadIdx.x & 31;
    if (w >= N_NODES) return;
    float2 xv0 = *(const float2*)&x[w * 64 + 2 * lane];
    float2 acc = xv0;
    int s = g_rowPtr[w], e = g_rowPtr[w + 1];
    int p = s;
    for (; p + 1 < e; p += 2) {
        int   c0 = __ldg(&g_colIdx[p]),     c1 = __ldg(&g_colIdx[p + 1]);
        float v0 = __ldg(&g_val[p]),        v1 = __ldg(&g_val[p + 1]);
        float2 a = *(const float2*)&x[c0 * 64 + 2 * lane];
        float2 bb = *(const float2*)&x[c1 * 64 + 2 * lane];
        acc.x = fmaf(v0, a.x, acc.x);  acc.y = fmaf(v0, a.y, acc.y);
        acc.x = fmaf(v1, bb.x, acc.x); acc.y = fmaf(v1, bb.y, acc.y);
    }
    if (p < e) {
        int c0 = __ldg(&g_colIdx[p]); float v0 = __ldg(&g_val[p]);
        float2 a = *(const float2*)&x[c0 * 64 + 2 * lane];
        acc.x = fmaf(v0, a.x, acc.x); acc.y = fmaf(v0, a.y, acc.y);
    }
    *(float2*)&g_Hcat[w * DIN + 2 * lane]      = xv0;
    *(float2*)&g_Hcat[w * DIN + 64 + 2 * lane] = acc;
}

// hop 2: src = Hcat[:,64:128], dst = Hcat[:,128:192]
__global__ void k_spmm2() {
    int w = (blockIdx.x * blockDim.x + threadIdx.x) >> 5;
    int lane = threadIdx.x & 31;
    if (w >= N_NODES) return;
    float2 acc = *(const float2*)&g_Hcat[w * DIN + 64 + 2 * lane];
    int s = g_rowPtr[w], e = g_rowPtr[w + 1];
    int p = s;
    for (; p + 1 < e; p += 2) {
        int   c0 = __ldg(&g_colIdx[p]),     c1 = __ldg(&g_colIdx[p + 1]);
        float v0 = __ldg(&g_val[p]),        v1 = __ldg(&g_val[p + 1]);
        float2 a = *(const float2*)&g_Hcat[c0 * DIN + 64 + 2 * lane];
        float2 bb = *(const float2*)&g_Hcat[c1 * DIN + 64 + 2 * lane];
        acc.x = fmaf(v0, a.x, acc.x);  acc.y = fmaf(v0, a.y, acc.y);
        acc.x = fmaf(v1, bb.x, acc.x); acc.y = fmaf(v1, bb.y, acc.y);
    }
    if (p < e) {
        int c0 = __ldg(&g_colIdx[p]); float v0 = __ldg(&g_val[p]);
        float2 a = *(const float2*)&g_Hcat[c0 * DIN + 64 + 2 * lane];
        acc.x = fmaf(v0, a.x, acc.x); acc.y = fmaf(v0, a.y, acc.y);
    }
    *(float2*)&g_Hcat[w * DIN + 128 + 2 * lane] = acc;
}

// H = Hcat @ (mask(W)/sigma)^T + b, with mask folded into Klim.
// Fused BN1 column-stat accumulation (sum, sumsq) via smem + global atomics.
__global__ void k_gemm(const float* __restrict__ W, const float* __restrict__ bias) {
    const int m0 = blockIdx.x * 64;
    const int n0 = blockIdx.y * 64;
    const int Klim = 64 * (blockIdx.y + 1);
    __shared__ float As[32][65];
    __shared__ float Bs[32][65];
    __shared__ float s_s[64], s_ss[64];
    const int tid = threadIdx.x;                // 256
    const int tx = tid & 15, ty = tid >> 4;
    const float invSig = 1.0f / g_sigma;
    float acc[4][4] = {};
    for (int k0 = 0; k0 < Klim; k0 += 32) {
#pragma unroll
        for (int r = 0; r < 8; ++r) {
            int e = tid + r * 256;
            int m = e >> 5, k = e & 31;
            As[k][m] = g_Hcat[(m0 + m) * DIN + k0 + k];
            Bs[k][m] = W[(n0 + m) * DIN + k0 + k] * invSig;
        }
        __syncthreads();
#pragma unroll
        for (int k = 0; k < 32; ++k) {
            float a[4], bb[4];
#pragma unroll
            for (int j = 0; j < 4; ++j) { a[j] = As[k][ty * 4 + j]; bb[j] = Bs[k][tx * 4 + j]; }
#pragma unroll
            for (int i = 0; i < 4; ++i)
#pragma unroll
                for (int j = 0; j < 4; ++j) acc[i][j] = fmaf(a[i], bb[j], acc[i][j]);
        }
        __syncthreads();
    }
    if (tid < 64) { s_s[tid] = 0.f; s_ss[tid] = 0.f; }
    __syncthreads();
    float cs[4] = {}, css[4] = {};
#pragma unroll
    for (int j = 0; j < 4; ++j) {
        int n = n0 + tx * 4 + j;
        float bv = bias[n];
#pragma unroll
        for (int i = 0; i < 4; ++i) {
            int m = m0 + ty * 4 + i;
            float v = acc[i][j] + bv;
            g_H[m * DOUT + n] = v;
            cs[j] += v; css[j] += v * v;
        }
        atomicAdd(&s_s[tx * 4 + j], cs[j]);
        atomicAdd(&s_ss[tx * 4 + j], css[j]);
    }
    __syncthreads();
    if (tid < 64) {
        atomicAdd(&g_sum[n0 + tid], s_s[tid]);
        atomicAdd(&g_sumsq[n0 + tid], s_ss[tid]);
    }
}

// BN1(apply) + segment avg/sum/max; bn1fin + segStart folded in (block per graph)
__global__ void k_pool(const int* __restrict__ batch,
                       const float* __restrict__ gamma, const float* __restrict__ beta) {
    __shared__ int sse[2];
    int g = blockIdx.x, c = threadIdx.x;        // 192 threads
    if (c < 2) {
        int target = g + c;
        int lo = 0, hi = N_NODES;
        while (lo < hi) {
            int mid = (lo + hi) >> 1;
            if (batch[mid] < target) lo = mid + 1; else hi = mid;
        }
        sse[c] = lo;
    }
    __syncthreads();
    int s = sse[0], e = sse[1];
    float mu = g_sum[c] * (1.0f / N_NODES);
    float var = g_sumsq[c] * (1.0f / N_NODES) - mu * mu;
    float rs = rsqrtf(var + BN_EPS);
    float ga = gamma[c], be = beta[c];
    float sum = 0.f, mx = -CUDART_INF_F;
    for (int r = s; r < e; ++r) {
        float v = ga * (g_H[r * DOUT + c] - mu) * rs + be;
        sum += v;
        mx = fmaxf(mx, v);
    }
    float cnt = (float)(e - s);
    g_Hg[g * D3 + c]            = sum / fmaxf(cnt, 1.f);
    g_Hg[g * D3 + DOUT + c]     = sum;
    g_Hg[g * D3 + 2 * DOUT + c] = mx;
}

// bn2 (stats recomputed per block) + fc1 + fc2 + fc3 + log_softmax + scratch re-zero
// 16 blocks x 384 threads, 4 graphs per block
__global__ void k_funnel(const float* __restrict__ g2, const float* __restrict__ be2,
                         const float* __restrict__ w1, const float* __restrict__ b1,
                         const float* __restrict__ w2, const float* __restrict__ b2,
                         const float* __restrict__ w3, const float* __restrict__ b3,
                         float* __restrict__ out) {
    __shared__ float smu[D3], srs[D3];
    __shared__ float sx[4][D3];
    __shared__ float a1s[4][H1DIM];
    __shared__ float a2s[4][H2DIM];
    int tid = threadIdx.x;                      // 384
    int r0 = blockIdx.x * 4;

    // bn2 stats (redundant per block, 64x576 in L2)
    for (int c = tid; c < D3; c += 384) {
        float s = 0.f, ss = 0.f;
        for (int r = 0; r < G_GRAPHS; ++r) {
            float v = g_Hg[r * D3 + c];
            s += v; ss += v * v;
        }
        float mu = s * (1.0f / G_GRAPHS);
        float var = ss * (1.0f / G_GRAPHS) - mu * mu;
        smu[c] = mu;
        srs[c] = rsqrtf(var + BN_EPS);
    }
    __syncthreads();
    // normalized inputs for our 4 rows
    for (int e = tid; e < 4 * D3; e += 384) {
        int r = e / D3, c = e % D3;
        sx[r][c] = g2[c] * (g_Hg[(r0 + r) * D3 + c] - smu[c]) * srs[c] + be2[c];
    }
    __syncthreads();
    // fc1: 384 outs
    {
        int o = tid;
        float a0 = b1[o], a1 = a0, a2 = a0, a3 = a0;
        const float4* wr = (const float4*)&w1[o * D3];
#pragma unroll 4
        for (int k4 = 0; k4 < D3 / 4; ++k4) {
            float4 w = wr[k4];
            int k = k4 * 4;
            a0 += w.x * sx[0][k] + w.y * sx[0][k + 1] + w.z * sx[0][k + 2] + w.w * sx[0][k + 3];
            a1 += w.x * sx[1][k] + w.y * sx[1][k + 1] + w.z * sx[1][k + 2] + w.w * sx[1][k + 3];
            a2 += w.x * sx[2][k] + w.y * sx[2][k + 1] + w.z * sx[2][k + 2] + w.w * sx[2][k + 3];
            a3 += w.x * sx[3][k] + w.y * sx[3][k + 1] + w.z * sx[3][k + 2] + w.w * sx[3][k + 3];
        }
        a1s[0][o] = fmaxf(a0, 0.f);
        a1s[1][o] = fmaxf(a1, 0.f);
        a1s[2][o] = fmaxf(a2, 0.f);
        a1s[3][o] = fmaxf(a3, 0.f);
    }
    __syncthreads();
    // fc2: 192 outs
    if (tid < H2DIM) {
        int o = tid;
        float a0 = b2[o], a1 = a0, a2 = a0, a3 = a0;
        const float4* wr = (const float4*)&w2[o * H1DIM];
#pragma unroll 4
        for (int k4 = 0; k4 < H1DIM / 4; ++k4) {
            float4 w = wr[k4];
            int k = k4 * 4;
            a0 += w.x * a1s[0][k] + w.y * a1s[0][k + 1] + w.z * a1s[0][k + 2] + w.w * a1s[0][k + 3];
            a1 += w.x * a1s[1][k] + w.y * a1s[1][k + 1] + w.z * a1s[1][k + 2] + w.w * a1s[1][k + 3];
            a2 += w.x * a1s[2][k] + w.y * a1s[2][k + 1] + w.z * a1s[2][k + 2] + w.w * a1s[2][k + 3];
            a3 += w.x * a1s[3][k] + w.y * a1s[3][k + 1] + w.z * a1s[3][k + 2] + w.w * a1s[3][k + 3];
        }
        a2s[0][o] = fmaxf(a0, 0.f);
        a2s[1][o] = fmaxf(a1, 0.f);
        a2s[2][o] = fmaxf(a2, 0.f);
        a2s[3][o] = fmaxf(a3, 0.f);
    }
    __syncthreads();
    // fc3 + log_softmax: warp w handles graph r0+w
    if (tid < 128) {
        int wrp = tid >> 5, lane = tid & 31;
        float z = -CUDART_INF_F;
        if (lane < NCLS) {
            z = b3[lane];
            const float* wr = &w3[lane * H2DIM];
            for (int k = 0; k < H2DIM; ++k) z = fmaf(wr[k], a2s[wrp][k], z);
        }
        float mx = z;
#pragma unroll
        for (int off = 16; off; off >>= 1) mx = fmaxf(mx, __shfl_xor_sync(0xffffffff, mx, off));
        float ex = (lane < NCLS) ? expf(z - mx) : 0.f;
        float sm = ex;
#pragma unroll
        for (int off = 16; off; off >>= 1) sm += __shfl_xor_sync(0xffffffff, sm, off);
        if (lane < NCLS) out[(r0 + wrp) * NCLS + lane] = z - mx - logf(sm);
    }
    // tail: re-zero scratch for next replay (grid covers 16*384 = 6144 threads)
    int gidx = blockIdx.x * 384 + tid;
    for (int i = gidx; i < N_NODES; i += 16 * 384) {
        g_deg[i] = 0.f;
        g_rowCnt[i] = 0;
    }
    if (gidx < DOUT) { g_sum[gidx] = 0.f; g_sumsq[gidx] = 0.f; }
}

// ---------------- launch ----------------
extern "C" void kernel_launch(void* const* d_in, const int* in_sizes, int n_in,
                              void* d_out, int out_size) {
    const float* x     = (const float*)d_in[0];
    const int*   ei    = (const int*)d_in[1];
    const int*   batch = (const int*)d_in[2];
    const float* Wo    = (const float*)d_in[3];
    const float* b     = (const float*)d_in[4];
    const float* u     = (const float*)d_in[5];
    const float* bn1g  = (const float*)d_in[6];
    const float* bn1b  = (const float*)d_in[7];
    const float* bn2g  = (const float*)d_in[8];
    const float* bn2b  = (const float*)d_in[9];
    const float* w1    = (const float*)d_in[10];
    const float* b1    = (const float*)d_in[11];
    const float* w2    = (const float*)d_in[12];
    const float* b2    = (const float*)d_in[13];
    const float* w3    = (const float*)d_in[14];
    const float* b3    = (const float*)d_in[15];
    float*       out   = (float*)d_out;

    k_degree<<<N_EDGES / 256, 256>>>(ei);
    k_scan<<<1, 1024>>>(Wo, u);
    k_build<<<N_EDGES / 256, 256>>>(ei);
    k_spmm1<<<N_NODES * 32 / 256, 256>>>(x);
    k_spmm2<<<N_NODES * 32 / 256, 256>>>();
    k_gemm<<<dim3(N_NODES / 64, DOUT / 64), 256>>>(Wo, b);
    k_pool<<<G_GRAPHS, DOUT>>>(batch, bn1g, bn1b);
    k_funnel<<<16, 384>>>(bn2g, bn2b, w1, b1, w2, b2, w3, b3, out);
}